// round 2
// baseline (speedup 1.0000x reference)
#include <cuda_runtime.h>

#define Bq   512
#define Tt   365
#define Ff   16
#define Hh   256
#define G4   1024
#define CLU  8       // CTAs per cluster
#define NCLU 16      // clusters (NCLU*CLU = 128 CTAs)
#define BC   32      // batch rows per cluster
#define NT   256
#define UPC  32      // hidden units per CTA
#define CPC  128     // packed gate columns per CTA
#define ZST  36      // zs row stride (floats)

typedef unsigned long long u64;

// ---------------------------------------------------------------------------
// Device scratch (L2-resident weights, global h-exchange buffers)
// g_w1: [16 + 256][1024]  rows = x-features then h1 units; cols packed per-CTA
// g_w2: [256 + 256][1024] rows = h1 units (W_ih2) then h2 units (W_hh2)
// packed col P: r = P>>7 (CTA rank), g = (P>>5)&3 (gate i/f/g/o), j = P&31
//   original col = g*256 + (r*32 + j)
// ---------------------------------------------------------------------------
__device__ float g_w1[(Ff + Hh) * G4];
__device__ float g_w2[(2 * Hh) * G4];
__device__ float g_b1[G4];
__device__ float g_b2[G4];
__device__ float g_h1[2][NCLU][Hh][BC];   // parity double-buffer
__device__ float g_h2[2][NCLU][Hh][BC];

// ---------------------------------------------------------------------------
// f32x2 helpers
// ---------------------------------------------------------------------------
__device__ __forceinline__ u64 dup2(float v) {
    u64 r; asm("mov.b64 %0, {%1, %1};" : "=l"(r) : "f"(v)); return r;
}
__device__ __forceinline__ u64 fma2(u64 a, u64 b, u64 c) {
    u64 d; asm("fma.rn.f32x2 %0, %1, %2, %3;" : "=l"(d) : "l"(a), "l"(b), "l"(c)); return d;
}
__device__ __forceinline__ float sigf(float x) { return 1.0f / (1.0f + __expf(-x)); }

__device__ __forceinline__ void cluster_sync_all() {
    asm volatile("barrier.cluster.arrive.aligned;" ::: "memory");
    asm volatile("barrier.cluster.wait.aligned;"   ::: "memory");
}

// ---------------------------------------------------------------------------
// Prep: gather weights into per-CTA packed column order, fuse biases.
// ---------------------------------------------------------------------------
__global__ void prep_kernel(const float* __restrict__ wih1, const float* __restrict__ whh1,
                            const float* __restrict__ bih1, const float* __restrict__ bhh1,
                            const float* __restrict__ wih2, const float* __restrict__ whh2,
                            const float* __restrict__ bih2, const float* __restrict__ bhh2) {
    int idx = blockIdx.x * blockDim.x + threadIdx.x;          // over 512*1024
    if (idx >= 2 * Hh * G4) return;
    int P = idx & (G4 - 1), k = idx >> 10;
    int r = P >> 7, rem = P & 127, g = rem >> 5, j = rem & 31;
    int oc = g * 256 + r * 32 + j;                            // original gate-col

    g_w2[idx] = (k < Hh) ? wih2[oc * Hh + k] : whh2[oc * Hh + (k - Hh)];
    if (k < Ff + Hh)
        g_w1[idx] = (k < Ff) ? wih1[oc * Ff + k] : whh1[oc * Hh + (k - Ff)];
    if (k == 0) {
        g_b1[P] = bih1[oc] + bhh1[oc];
        g_b2[P] = bih2[oc] + bhh2[oc];
    }
}

// ---------------------------------------------------------------------------
// Fused 2-layer LSTM, cluster of 8 CTAs per 32 batch rows.
// Gate phase: thread = (cg = tid&63 -> cols 2cg,2cg+1 ; bg = tid>>6 -> 8 batch)
// Update phase: thread = (uu = tid&31 -> unit ; bq = tid>>5 -> 4 batch), c in regs
// ---------------------------------------------------------------------------
__global__ void __cluster_dims__(CLU, 1, 1) __launch_bounds__(NT, 1)
lstm_kernel(const float* __restrict__ x,
            const float* __restrict__ wlin, const float* __restrict__ blin,
            float* __restrict__ out) {
    __shared__ float zs[CPC * ZST];
    __shared__ float xs[Ff * BC];

    const int tid = threadIdx.x;
    const int cg = tid & 63, bg = tid >> 6;
    const int uu = tid & 31, bq = tid >> 5;
    unsigned rank; asm("mov.u32 %0, %%cluster_ctarank;" : "=r"(rank));
    const int clu = blockIdx.x >> 3;
    const int PB = rank * CPC;
    const int U0 = rank * UPC;

    const float* w1x = &g_w1[PB + 2 * cg];                 // rows 0..15 (x)
    const float* w1h = &g_w1[Ff * G4 + PB + 2 * cg];       // rows 16..271 (h1)
    const float* w2a = &g_w2[PB + 2 * cg];                 // rows 0..255 (h1 -> ih2)
    const float* w2b = &g_w2[Hh * G4 + PB + 2 * cg];       // rows 256..511 (h2 -> hh2)

    const float2 bv1 = *(const float2*)&g_b1[PB + 2 * cg];
    const float2 bv2 = *(const float2*)&g_b2[PB + 2 * cg];
    const u64 bi10 = dup2(bv1.x), bi11 = dup2(bv1.y);
    const u64 bi20 = dup2(bv2.x), bi21 = dup2(bv2.y);

    // zero parity-0 state for this CTA's unit slice
    for (int i = tid; i < UPC * BC; i += NT) {
        int u = i >> 5, b = i & 31;
        g_h1[0][clu][U0 + u][b] = 0.f;
        g_h2[0][clu][U0 + u][b] = 0.f;
    }
    float c1[4] = {0.f, 0.f, 0.f, 0.f};
    float c2[4] = {0.f, 0.f, 0.f, 0.f};
    cluster_sync_all();

    const long xbase = (long)(clu * BC) * Tt * Ff;

    for (int t = 0; t < Tt; ++t) {
        const int A = t & 1, Bp = A ^ 1;

        // ---- stage x_t (xs[f][b]) ----
        for (int i = tid; i < Ff * BC; i += NT) {
            int f = i & 15, b = i >> 4;
            xs[f * BC + b] = x[xbase + ((long)b * Tt + t) * Ff + f];
        }
        __syncthreads();

        // ================= LAYER 1 gates =================
        {
            u64 a00 = bi10, a01 = bi10, a02 = bi10, a03 = bi10;
            u64 a10 = bi11, a11 = bi11, a12 = bi11, a13 = bi11;
            const float* xr = xs + bg * 8;
            #pragma unroll
            for (int k = 0; k < Ff; ++k) {
                float2 w = *(const float2*)(w1x + (size_t)k * G4);
                u64 w0 = dup2(w.x), w1 = dup2(w.y);
                ulonglong2 hA = *(const ulonglong2*)(xr + k * BC);
                ulonglong2 hB = *(const ulonglong2*)(xr + k * BC + 4);
                a00 = fma2(w0, hA.x, a00); a01 = fma2(w0, hA.y, a01);
                a02 = fma2(w0, hB.x, a02); a03 = fma2(w0, hB.y, a03);
                a10 = fma2(w1, hA.x, a10); a11 = fma2(w1, hA.y, a11);
                a12 = fma2(w1, hB.x, a12); a13 = fma2(w1, hB.y, a13);
            }
            const float* h1r = &g_h1[A][clu][0][bg * 8];
            #pragma unroll 8
            for (int k = 0; k < Hh; ++k) {
                float2 w = __ldg((const float2*)(w1h + (size_t)k * G4));
                ulonglong2 hA = __ldcg((const ulonglong2*)(h1r + k * BC));
                ulonglong2 hB = __ldcg((const ulonglong2*)(h1r + k * BC + 4));
                u64 w0 = dup2(w.x), w1 = dup2(w.y);
                a00 = fma2(w0, hA.x, a00); a01 = fma2(w0, hA.y, a01);
                a02 = fma2(w0, hB.x, a02); a03 = fma2(w0, hB.y, a03);
                a10 = fma2(w1, hA.x, a10); a11 = fma2(w1, hA.y, a11);
                a12 = fma2(w1, hB.x, a12); a13 = fma2(w1, hB.y, a13);
            }
            float* zp = &zs[(2 * cg) * ZST + bg * 8];
            *(ulonglong2*)(zp)            = make_ulonglong2(a00, a01);
            *(ulonglong2*)(zp + 4)        = make_ulonglong2(a02, a03);
            *(ulonglong2*)(zp + ZST)      = make_ulonglong2(a10, a11);
            *(ulonglong2*)(zp + ZST + 4)  = make_ulonglong2(a12, a13);
        }
        __syncthreads();

        // ================= LAYER 1 update =================
        {
            const float* zp = &zs[uu * ZST + bq * 4];
            float4 vi = *(const float4*)(zp);
            float4 vf = *(const float4*)(zp + 32 * ZST);
            float4 vg = *(const float4*)(zp + 64 * ZST);
            float4 vo = *(const float4*)(zp + 96 * ZST);
            float hn[4];
            c1[0] = sigf(vf.x) * c1[0] + sigf(vi.x) * tanhf(vg.x); hn[0] = sigf(vo.x) * tanhf(c1[0]);
            c1[1] = sigf(vf.y) * c1[1] + sigf(vi.y) * tanhf(vg.y); hn[1] = sigf(vo.y) * tanhf(c1[1]);
            c1[2] = sigf(vf.z) * c1[2] + sigf(vi.z) * tanhf(vg.z); hn[2] = sigf(vo.z) * tanhf(c1[2]);
            c1[3] = sigf(vf.w) * c1[3] + sigf(vi.w) * tanhf(vg.w); hn[3] = sigf(vo.w) * tanhf(c1[3]);
            __stcg((float4*)&g_h1[Bp][clu][U0 + uu][bq * 4],
                   make_float4(hn[0], hn[1], hn[2], hn[3]));
        }
        cluster_sync_all();   // h1_new visible cluster-wide

        // ================= LAYER 2 gates =================
        {
            u64 a00 = bi20, a01 = bi20, a02 = bi20, a03 = bi20;
            u64 a10 = bi21, a11 = bi21, a12 = bi21, a13 = bi21;
            const float* h1n = &g_h1[Bp][clu][0][bg * 8];
            #pragma unroll 8
            for (int k = 0; k < Hh; ++k) {
                float2 w = __ldg((const float2*)(w2a + (size_t)k * G4));
                ulonglong2 hA = __ldcg((const ulonglong2*)(h1n + k * BC));
                ulonglong2 hB = __ldcg((const ulonglong2*)(h1n + k * BC + 4));
                u64 w0 = dup2(w.x), w1 = dup2(w.y);
                a00 = fma2(w0, hA.x, a00); a01 = fma2(w0, hA.y, a01);
                a02 = fma2(w0, hB.x, a02); a03 = fma2(w0, hB.y, a03);
                a10 = fma2(w1, hA.x, a10); a11 = fma2(w1, hA.y, a11);
                a12 = fma2(w1, hB.x, a12); a13 = fma2(w1, hB.y, a13);
            }
            const float* h2r = &g_h2[A][clu][0][bg * 8];
            #pragma unroll 8
            for (int k = 0; k < Hh; ++k) {
                float2 w = __ldg((const float2*)(w2b + (size_t)k * G4));
                ulonglong2 hA = __ldcg((const ulonglong2*)(h2r + k * BC));
                ulonglong2 hB = __ldcg((const ulonglong2*)(h2r + k * BC + 4));
                u64 w0 = dup2(w.x), w1 = dup2(w.y);
                a00 = fma2(w0, hA.x, a00); a01 = fma2(w0, hA.y, a01);
                a02 = fma2(w0, hB.x, a02); a03 = fma2(w0, hB.y, a03);
                a10 = fma2(w1, hA.x, a10); a11 = fma2(w1, hA.y, a11);
                a12 = fma2(w1, hB.x, a12); a13 = fma2(w1, hB.y, a13);
            }
            float* zp = &zs[(2 * cg) * ZST + bg * 8];
            *(ulonglong2*)(zp)            = make_ulonglong2(a00, a01);
            *(ulonglong2*)(zp + 4)        = make_ulonglong2(a02, a03);
            *(ulonglong2*)(zp + ZST)      = make_ulonglong2(a10, a11);
            *(ulonglong2*)(zp + ZST + 4)  = make_ulonglong2(a12, a13);
        }
        __syncthreads();

        // ================= LAYER 2 update =================
        {
            const float* zp = &zs[uu * ZST + bq * 4];
            float4 vi = *(const float4*)(zp);
            float4 vf = *(const float4*)(zp + 32 * ZST);
            float4 vg = *(const float4*)(zp + 64 * ZST);
            float4 vo = *(const float4*)(zp + 96 * ZST);
            float hn[4];
            c2[0] = sigf(vf.x) * c2[0] + sigf(vi.x) * tanhf(vg.x); hn[0] = sigf(vo.x) * tanhf(c2[0]);
            c2[1] = sigf(vf.y) * c2[1] + sigf(vi.y) * tanhf(vg.y); hn[1] = sigf(vo.y) * tanhf(c2[1]);
            c2[2] = sigf(vf.z) * c2[2] + sigf(vi.z) * tanhf(vg.z); hn[2] = sigf(vo.z) * tanhf(c2[2]);
            c2[3] = sigf(vf.w) * c2[3] + sigf(vi.w) * tanhf(vg.w); hn[3] = sigf(vo.w) * tanhf(c2[3]);
            __stcg((float4*)&g_h2[Bp][clu][U0 + uu][bq * 4],
                   make_float4(hn[0], hn[1], hn[2], hn[3]));
        }
        cluster_sync_all();   // h2_new visible cluster-wide
    }

    // ================= linear head (rank 0 per cluster) =================
    // final h2 is at parity (Tt & 1) == 1
    if (rank == 0 && tid < BC) {
        const int b = tid;
        float s = blin[0];
        #pragma unroll 8
        for (int u = 0; u < Hh; ++u)
            s += __ldcg(&g_h2[1][clu][u][b]) * __ldg(&wlin[u]);
        out[clu * BC + b] = s;
    }
}

// ---------------------------------------------------------------------------
extern "C" void kernel_launch(void* const* d_in, const int* in_sizes, int n_in,
                              void* d_out, int out_size) {
    const float* x    = (const float*)d_in[0];
    const float* wih1 = (const float*)d_in[1];
    const float* whh1 = (const float*)d_in[2];
    const float* bih1 = (const float*)d_in[3];
    const float* bhh1 = (const float*)d_in[4];
    const float* wih2 = (const float*)d_in[5];
    const float* whh2 = (const float*)d_in[6];
    const float* bih2 = (const float*)d_in[7];
    const float* bhh2 = (const float*)d_in[8];
    const float* wlin = (const float*)d_in[9];
    const float* blin = (const float*)d_in[10];
    float* out = (float*)d_out;

    prep_kernel<<<(2 * Hh * G4 + 255) / 256, 256>>>(wih1, whh1, bih1, bhh1,
                                                    wih2, whh2, bih2, bhh2);
    lstm_kernel<<<NCLU * CLU, NT>>>(x, wlin, blin, out);
}

// round 3
// speedup vs baseline: 2.5465x; 2.5465x over previous
#include <cuda_runtime.h>
#include <cuda_fp16.h>

#define Bq   512
#define Tt   365
#define Ff   16
#define Hh   256
#define G4   1024
#define NC   128     // CTAs (1 per SM-ish)
#define BS   4       // batch rows per CTA
#define NT   512     // threads per CTA (2 gate cols each)

typedef unsigned long long u64;

// ---------------------------------------------------------------------------
// Device scratch: fp16 weights (L2-resident), fp32 fused biases.
// g_w1: [16 + 256 rows][1024 cols]  (W_ih1 rows then W_hh1 rows), natural col order
// g_w2: [256 rows][512 col-pairs][wa0,wa1,wb0,wb1]  (W_ih2 & W_hh2 interleaved)
// ---------------------------------------------------------------------------
__device__ __half g_w1[(Ff + Hh) * G4];
__device__ __half g_w2[Hh * 2 * G4];
__device__ float  g_b1[G4];
__device__ float  g_b2[G4];

// ---------------------------------------------------------------------------
// helpers
// ---------------------------------------------------------------------------
__device__ __forceinline__ u64 fma2(u64 a, u64 b, u64 c) {
    u64 d; asm("fma.rn.f32x2 %0, %1, %2, %3;" : "=l"(d) : "l"(a), "l"(b), "l"(c)); return d;
}
__device__ __forceinline__ u64 h2f(unsigned hw) {
    __half2 h = *reinterpret_cast<__half2*>(&hw);
    float2 f = __half22float2(h);
    u64 r; asm("mov.b64 %0, {%1, %2};" : "=l"(r) : "f"(f.x), "f"(f.y)); return r;
}
__device__ __forceinline__ float sigf(float x) { return 1.0f / (1.0f + __expf(-x)); }

// ---------------------------------------------------------------------------
// Prep: fp32 -> fp16, pack layouts, fuse biases.
// ---------------------------------------------------------------------------
__global__ void prep_kernel(const float* __restrict__ wih1, const float* __restrict__ whh1,
                            const float* __restrict__ bih1, const float* __restrict__ bhh1,
                            const float* __restrict__ wih2, const float* __restrict__ whh2,
                            const float* __restrict__ bih2, const float* __restrict__ bhh2) {
    int idx = blockIdx.x * blockDim.x + threadIdx.x;

    // g_w2: idx over 256*2048
    if (idx < Hh * 2 * G4) {
        int k = idx >> 11, r = idx & 2047;
        int cp = r >> 2, q = r & 3;
        float v;
        if (q < 2) { int col = 2 * cp + q;       v = wih2[col * Hh + k]; }
        else       { int col = 2 * cp + (q - 2); v = whh2[col * Hh + k]; }
        g_w2[idx] = __float2half_rn(v);
    }
    // g_w1: idx over 272*1024
    if (idx < (Ff + Hh) * G4) {
        int k = idx >> 10, col = idx & 1023;
        float v = (k < Ff) ? wih1[col * Ff + k] : whh1[col * Hh + (k - Ff)];
        g_w1[idx] = __float2half_rn(v);
    }
    if (idx < G4) {
        g_b1[idx] = bih1[idx] + bhh1[idx];
        g_b2[idx] = bih2[idx] + bhh2[idx];
    }
}

// ---------------------------------------------------------------------------
// Fused 2-layer LSTM. One CTA = 4 batch rows, full recurrence, state in SMEM.
// Gate phase: thread tid -> gate cols (2*tid, 2*tid+1), all 4 batch rows.
// Update phase: unit u = tid&255, batch pair bp = tid>>8 (2 rows), c in regs.
// h stored DUPLICATED: hd[u][8] = {h0,h0,h1,h1,h2,h2,h3,h3} -> LDS.128 gives
// ready-made f32x2 operands.
// ---------------------------------------------------------------------------
__global__ void __launch_bounds__(NT, 1)
lstm_kernel(const float* __restrict__ x,
            const float* __restrict__ wlin, const float* __restrict__ blin,
            float* __restrict__ out) {
    __shared__ float zs[BS * G4];      // zs[b][col]
    __shared__ float h1d[Hh * 8];      // duplicated h1
    __shared__ float h2d[Hh * 8];      // duplicated h2
    __shared__ float xs[Ff * 8];       // duplicated x_t

    const int tid = threadIdx.x;
    const int b0  = blockIdx.x * BS;
    const int u   = tid & 255;
    const int bp  = tid >> 8;

    // zero state
    if (tid < Hh) {
        float4 z4 = make_float4(0.f, 0.f, 0.f, 0.f);
        *(float4*)&h1d[tid * 8]     = z4;  *(float4*)&h1d[tid * 8 + 4] = z4;
        *(float4*)&h2d[tid * 8]     = z4;  *(float4*)&h2d[tid * 8 + 4] = z4;
    }
    float c1a = 0.f, c1b = 0.f, c2a = 0.f, c2b = 0.f;

    const u64 bias1 = *(const u64*)&g_b1[2 * tid];
    const u64 bias2 = *(const u64*)&g_b2[2 * tid];

    const __half* w1x = &g_w1[2 * tid];               // rows 0..15
    const __half* w1h = &g_w1[Ff * G4 + 2 * tid];     // rows 16..271
    const __half* w2p = &g_w2[4 * tid];               // packed [wa2|wb2]

    __syncthreads();

    for (int t = 0; t < Tt; ++t) {
        // ---- stage x_t duplicated: xs[f][2b],[2b+1] ----
        if (tid < Ff * BS) {
            int b = tid >> 4, f = tid & 15;
            float v = __ldg(&x[((size_t)(b0 + b) * Tt + t) * Ff + f]);
            *(float2*)&xs[f * 8 + 2 * b] = make_float2(v, v);
        }
        __syncthreads();   // xs ready; h1d/h2d from prev step ready

        // ================= LAYER 1 gates =================
        {
            u64 a0 = bias1, a1 = bias1, a2 = bias1, a3 = bias1;
            #pragma unroll
            for (int k = 0; k < Ff; ++k) {
                u64 w = h2f(__ldg((const unsigned*)(w1x + (size_t)k * G4)));
                ulonglong2 hA = *(const ulonglong2*)&xs[k * 8];
                ulonglong2 hB = *(const ulonglong2*)&xs[k * 8 + 4];
                a0 = fma2(w, hA.x, a0); a1 = fma2(w, hA.y, a1);
                a2 = fma2(w, hB.x, a2); a3 = fma2(w, hB.y, a3);
            }
            #pragma unroll 8
            for (int k = 0; k < Hh; ++k) {
                u64 w = h2f(__ldg((const unsigned*)(w1h + (size_t)k * G4)));
                ulonglong2 hA = *(const ulonglong2*)&h1d[k * 8];
                ulonglong2 hB = *(const ulonglong2*)&h1d[k * 8 + 4];
                a0 = fma2(w, hA.x, a0); a1 = fma2(w, hA.y, a1);
                a2 = fma2(w, hB.x, a2); a3 = fma2(w, hB.y, a3);
            }
            *(u64*)&zs[0 * G4 + 2 * tid] = a0;
            *(u64*)&zs[1 * G4 + 2 * tid] = a1;
            *(u64*)&zs[2 * G4 + 2 * tid] = a2;
            *(u64*)&zs[3 * G4 + 2 * tid] = a3;
        }
        __syncthreads();

        // ================= LAYER 1 update =================
        {
            const int b = 2 * bp;
            {
                const float* zp = &zs[b * G4 + u];
                float zi = zp[0], zf = zp[Hh], zg = zp[2 * Hh], zo = zp[3 * Hh];
                c1a = sigf(zf) * c1a + sigf(zi) * tanhf(zg);
                float h = sigf(zo) * tanhf(c1a);
                *(float2*)&h1d[u * 8 + 2 * b] = make_float2(h, h);
            }
            {
                const float* zp = &zs[(b + 1) * G4 + u];
                float zi = zp[0], zf = zp[Hh], zg = zp[2 * Hh], zo = zp[3 * Hh];
                c1b = sigf(zf) * c1b + sigf(zi) * tanhf(zg);
                float h = sigf(zo) * tanhf(c1b);
                *(float2*)&h1d[u * 8 + 2 * (b + 1)] = make_float2(h, h);
            }
        }
        __syncthreads();

        // ================= LAYER 2 gates =================
        {
            u64 a0 = bias2, a1 = bias2, a2 = bias2, a3 = bias2;
            #pragma unroll 8
            for (int k = 0; k < Hh; ++k) {
                uint2 wp = __ldg((const uint2*)(w2p + (size_t)k * 2 * G4));
                u64 wa = h2f(wp.x);
                u64 wb = h2f(wp.y);
                ulonglong2 hA1 = *(const ulonglong2*)&h1d[k * 8];
                ulonglong2 hB1 = *(const ulonglong2*)&h1d[k * 8 + 4];
                ulonglong2 hA2 = *(const ulonglong2*)&h2d[k * 8];
                ulonglong2 hB2 = *(const ulonglong2*)&h2d[k * 8 + 4];
                a0 = fma2(wa, hA1.x, a0); a1 = fma2(wa, hA1.y, a1);
                a2 = fma2(wa, hB1.x, a2); a3 = fma2(wa, hB1.y, a3);
                a0 = fma2(wb, hA2.x, a0); a1 = fma2(wb, hA2.y, a1);
                a2 = fma2(wb, hB2.x, a2); a3 = fma2(wb, hB2.y, a3);
            }
            *(u64*)&zs[0 * G4 + 2 * tid] = a0;
            *(u64*)&zs[1 * G4 + 2 * tid] = a1;
            *(u64*)&zs[2 * G4 + 2 * tid] = a2;
            *(u64*)&zs[3 * G4 + 2 * tid] = a3;
        }
        __syncthreads();

        // ================= LAYER 2 update =================
        {
            const int b = 2 * bp;
            {
                const float* zp = &zs[b * G4 + u];
                float zi = zp[0], zf = zp[Hh], zg = zp[2 * Hh], zo = zp[3 * Hh];
                c2a = sigf(zf) * c2a + sigf(zi) * tanhf(zg);
                float h = sigf(zo) * tanhf(c2a);
                *(float2*)&h2d[u * 8 + 2 * b] = make_float2(h, h);
            }
            {
                const float* zp = &zs[(b + 1) * G4 + u];
                float zi = zp[0], zf = zp[Hh], zg = zp[2 * Hh], zo = zp[3 * Hh];
                c2b = sigf(zf) * c2b + sigf(zi) * tanhf(zg);
                float h = sigf(zo) * tanhf(c2b);
                *(float2*)&h2d[u * 8 + 2 * (b + 1)] = make_float2(h, h);
            }
        }
        __syncthreads();   // h2d ready for next step's L2 gates / final head
    }

    // ================= linear head =================
    if (tid < 32 * BS) {
        int b = tid >> 5, lane = tid & 31;
        float s = 0.f;
        #pragma unroll
        for (int k = lane; k < Hh; k += 32) s += h2d[k * 8 + 2 * b] * __ldg(&wlin[k]);
        #pragma unroll
        for (int off = 16; off; off >>= 1) s += __shfl_xor_sync(0xffffffffu, s, off);
        if (lane == 0) out[b0 + b] = s + blin[0];
    }
}

// ---------------------------------------------------------------------------
extern "C" void kernel_launch(void* const* d_in, const int* in_sizes, int n_in,
                              void* d_out, int out_size) {
    const float* x    = (const float*)d_in[0];
    const float* wih1 = (const float*)d_in[1];
    const float* whh1 = (const float*)d_in[2];
    const float* bih1 = (const float*)d_in[3];
    const float* bhh1 = (const float*)d_in[4];
    const float* wih2 = (const float*)d_in[5];
    const float* whh2 = (const float*)d_in[6];
    const float* bih2 = (const float*)d_in[7];
    const float* bhh2 = (const float*)d_in[8];
    const float* wlin = (const float*)d_in[9];
    const float* blin = (const float*)d_in[10];
    float* out = (float*)d_out;

    prep_kernel<<<(Hh * 2 * G4 + 255) / 256, 256>>>(wih1, whh1, bih1, bhh1,
                                                    wih2, whh2, bih2, bhh2);
    lstm_kernel<<<NC, NT>>>(x, wlin, blin, out);
}